// round 2
// baseline (speedup 1.0000x reference)
#include <cuda_runtime.h>
#include <cstdint>

// Segment-mean over sorted segment ids.
// atom_hiddens: [n_atoms, 128] f32 ; segment_ids: [n_atoms] i32 (sorted) ;
// out: [n_mols, 128] f32 where out[m] = mean of rows whose id == m.

static constexpr int HIDDEN = 128;

__device__ __forceinline__ int lower_bound_dev(const int* __restrict__ ids, int n, int key) {
    int lo = 0, hi = n;
    while (lo < hi) {
        int mid = (lo + hi) >> 1;
        if (__ldg(ids + mid) < key) lo = mid + 1;
        else                        hi = mid;
    }
    return lo;
}

__global__ __launch_bounds__(128, 16)
void seg_mean_kernel(const float* __restrict__ x,
                     const int*   __restrict__ ids,
                     float*       __restrict__ out,
                     int n_atoms) {
    const int mol  = blockIdx.x;
    const int t    = threadIdx.x;
    const int warp = t >> 5;
    const int lane = t & 31;

    __shared__ int s_range[2];
    __shared__ alignas(16) float s_part[4][HIDDEN];   // 16B-aligned for STS.128

    // Two threads (in different warps) do the two binary searches in parallel.
    if (t == 0)       s_range[0] = lower_bound_dev(ids, n_atoms, mol);
    else if (t == 32) s_range[1] = lower_bound_dev(ids, n_atoms, mol + 1);
    __syncthreads();

    const int start = s_range[0];
    const int end   = s_range[1];
    const int count = end - start;

    // Warp w accumulates rows start+w, start+w+4, ... ; lane covers 4 columns.
    float4 acc = make_float4(0.f, 0.f, 0.f, 0.f);
    #pragma unroll 5
    for (int r = start + warp; r < end; r += 4) {
        const float4 v = __ldg(reinterpret_cast<const float4*>(
                               x + (size_t)r * HIDDEN) + lane);
        acc.x += v.x; acc.y += v.y; acc.z += v.z; acc.w += v.w;
    }

    // Conflict-free partial store (STS.128), then 4-way add per output column.
    *reinterpret_cast<float4*>(&s_part[warp][lane * 4]) = acc;
    __syncthreads();

    const float sum = s_part[0][t] + s_part[1][t] + s_part[2][t] + s_part[3][t];
    const float inv = (count > 0) ? (1.0f / (float)count) : 0.0f;
    out[(size_t)mol * HIDDEN + t] = sum * inv;
}

extern "C" void kernel_launch(void* const* d_in, const int* in_sizes, int n_in,
                              void* d_out, int out_size) {
    const float* atom_hiddens = (const float*)d_in[0];
    const int*   segment_ids  = (const int*)d_in[1];
    // d_in[2] is n_mols on device; we derive it from out_size instead.
    float* out = (float*)d_out;

    const int n_atoms = in_sizes[1];          // segment_ids element count
    const int n_mols  = out_size / HIDDEN;    // output rows

    seg_mean_kernel<<<n_mols, 128>>>(atom_hiddens, segment_ids, out, n_atoms);
}

// round 3
// speedup vs baseline: 1.6591x; 1.6591x over previous
#include <cuda_runtime.h>
#include <cstdint>

// Segment-mean over sorted segment ids, two-phase:
//   A) boundary scan builds seg_start[] offsets table
//   B) one CTA per molecule streams its rows and writes the mean
// atom_hiddens: [n_atoms, 128] f32 ; segment_ids: [n_atoms] i32 (sorted) ;
// out: [n_mols, 128] f32.

static constexpr int HIDDEN = 128;
static constexpr int MAX_MOLS = 4 * 1024 * 1024;   // scratch capacity (16 MB)

__device__ int g_seg_start[MAX_MOLS + 1];

// ---- Kernel A: find segment boundaries (one pass over ids, coalesced) ----
__global__ __launch_bounds__(256)
void seg_offsets_kernel(const int* __restrict__ ids, int n_atoms, int n_mols) {
    const int i = blockIdx.x * 256 + threadIdx.x;
    if (i >= n_atoms) return;
    const int id = __ldg(ids + i);
    if (i == 0) {
        g_seg_start[id] = 0;
        g_seg_start[n_mols] = n_atoms;
    } else if (__ldg(ids + i - 1) != id) {
        g_seg_start[id] = i;
    }
}

// ---- Kernel B: stream + reduce, one CTA per molecule ----
__global__ __launch_bounds__(128, 16)
void seg_mean_kernel(const float* __restrict__ x,
                     float*       __restrict__ out) {
    const int mol  = blockIdx.x;
    const int t    = threadIdx.x;
    const int warp = t >> 5;
    const int lane = t & 31;

    __shared__ alignas(16) float s_part[4][HIDDEN];

    // Broadcast loads: one request per warp, adjacent CTAs share cache lines.
    const int start = __ldg(&g_seg_start[mol]);
    const int end   = __ldg(&g_seg_start[mol + 1]);
    const int count = end - start;

    // Warp w accumulates rows start+w, start+w+4, ... ; lane covers 4 columns.
    float4 acc = make_float4(0.f, 0.f, 0.f, 0.f);
    #pragma unroll 5
    for (int r = start + warp; r < end; r += 4) {
        const float4 v = __ldg(reinterpret_cast<const float4*>(
                               x + (size_t)r * HIDDEN) + lane);
        acc.x += v.x; acc.y += v.y; acc.z += v.z; acc.w += v.w;
    }

    // Conflict-free partial store (STS.128), then 4-way add per output column.
    *reinterpret_cast<float4*>(&s_part[warp][lane * 4]) = acc;
    __syncthreads();

    const float sum = s_part[0][t] + s_part[1][t] + s_part[2][t] + s_part[3][t];
    const float inv = (count > 0) ? (1.0f / (float)count) : 0.0f;
    out[(size_t)mol * HIDDEN + t] = sum * inv;
}

extern "C" void kernel_launch(void* const* d_in, const int* in_sizes, int n_in,
                              void* d_out, int out_size) {
    const float* atom_hiddens = (const float*)d_in[0];
    const int*   segment_ids  = (const int*)d_in[1];
    float* out = (float*)d_out;

    const int n_atoms = in_sizes[1];          // segment_ids element count
    const int n_mols  = out_size / HIDDEN;    // output rows

    seg_offsets_kernel<<<(n_atoms + 255) / 256, 256>>>(segment_ids, n_atoms, n_mols);
    seg_mean_kernel<<<n_mols, 128>>>(atom_hiddens, out);
}